// round 7
// baseline (speedup 1.0000x reference)
#include <cuda_runtime.h>
#include <cuda_bf16.h>

#define NN 8192
#define BB 4096
#define EPSV 1e-7f
// Levels: 0:[0,8) 1:[8,136) 2:[136,2184) 3:[2184,8192). All parents < 2184.
#define L1_BEG 8
#define L2_BEG 136
#define ANC_SENT 2184
#define TBL 2192

__device__ unsigned short g_anc1[NN];   // parent index, sentinel = ANC_SENT
__device__ float          g_partial[BB];
__device__ int            g_done;

__global__ void anc_setup_kernel(const int* __restrict__ parent, int n) {
    int c = blockIdx.x * blockDim.x + threadIdx.x;
    if (c < n) {
        int a1 = parent[c];
        g_anc1[c] = (unsigned short)((a1 >= 0) ? a1 : ANC_SENT);
    }
}

__device__ __forceinline__ float fsigmoid(float x) {
    return __fdividef(1.0f, 1.0f + __expf(-x));
}

// scf[j] holds the sign-packed running value: sign = own target, magnitude:
//   after stage pass : sigmoid(pred[j])
//   after level pass : cumulative chain product cp[j]
// Sentinel scf[ANC_SENT] = -1.0f  (|.|=1, sign => root mask 1).
__global__ __launch_bounds__(256, 7)
void cond_sigmoid_kernel(const float* __restrict__ pred,
                         const float* __restrict__ target,
                         float* __restrict__ out) {
    __shared__ float scf[TBL];
    __shared__ float red[8];
    __shared__ double dred[8];
    __shared__ int    is_last;

    const int b   = blockIdx.x;
    const int tid = threadIdx.x;
    const size_t row = (size_t)b * NN;
    const float4* pr = (const float4*)(pred   + row);
    const float4* tg = (const float4*)(target + row);
    float* oc = out + 1 + row;

    // Stage: packed sigmoid for internal nodes [0, 2184).
    for (int i = tid; i < ANC_SENT / 4; i += 256) {
        float4 v = pr[i];
        float4 t = tg[i];
        float4 s;
        s.x = fsigmoid(v.x); s.y = fsigmoid(v.y);
        s.z = fsigmoid(v.z); s.w = fsigmoid(v.w);
        s.x = (t.x > 0.0f) ? -s.x : s.x;
        s.y = (t.y > 0.0f) ? -s.y : s.y;
        s.z = (t.z > 0.0f) ? -s.z : s.z;
        s.w = (t.w > 0.0f) ? -s.w : s.w;
        ((float4*)scf)[i] = s;
    }
    if (tid == 0) scf[ANC_SENT] = -1.0f;
    __syncthreads();

    float acc = 0.0f;

    // Roots [0,8): cp = p, mask = 1.
    if (tid < L1_BEG) {
        int j = tid;
        float s = scf[j];
        float p = fabsf(s);
        oc[j] = p;
        float t = (s < 0.0f) ? 1.0f : 0.0f;
        float q = fminf(fmaxf(p, EPSV), 1.0f - EPSV);
        acc += __logf(1.0f - fabsf(t - q));          // coef always 1 for roots
    }
    // Level 1 [8,136): parents are roots (cp = p for roots, already in table).
    if (tid < 128) {
        int j = L1_BEG + tid;
        float s  = scf[j];
        float sp_ = scf[g_anc1[j]];
        float p  = fabsf(s);
        float cp = p * fabsf(sp_);
        scf[j] = (s < 0.0f) ? -cp : cp;
        oc[j]  = cp;
        float t = (s < 0.0f) ? 1.0f : 0.0f;
        float q = fminf(fmaxf(p, EPSV), 1.0f - EPSV);
        bool take = (s < 0.0f) || (sp_ < 0.0f);
        acc += take ? __logf(1.0f - fabsf(t - q)) : 0.0f;
    }
    __syncthreads();

    // Level 2 [136,2184): parents are level-1 (finalized above).
    for (int j = L2_BEG + tid; j < ANC_SENT; j += 256) {
        float s  = scf[j];
        float sp_ = scf[g_anc1[j]];
        float p  = fabsf(s);
        float cp = p * fabsf(sp_);
        scf[j] = (s < 0.0f) ? -cp : cp;
        oc[j]  = cp;
        float t = (s < 0.0f) ? 1.0f : 0.0f;
        float q = fminf(fmaxf(p, EPSV), 1.0f - EPSV);
        bool take = (s < 0.0f) || (sp_ < 0.0f);
        acc += take ? __logf(1.0f - fabsf(t - q)) : 0.0f;
    }
    __syncthreads();

    // Leaves [2184, 8192): one LDS.32 gather per element.
    const uint2* anc1v = (const uint2*)g_anc1;
    #pragma unroll 2
    for (int i = ANC_SENT / 4 + tid; i < NN / 4; i += 256) {
        float4 pv = pr[i];
        float4 tv = tg[i];
        uint2 aw = anc1v[i];
        int a0 = aw.x & 0xFFFF, a1i = aw.x >> 16;
        int a2i = aw.y & 0xFFFF, a3i = aw.y >> 16;

        float s0 = scf[a0], s1 = scf[a1i], s2 = scf[a2i], s3 = scf[a3i];

        float p0 = fsigmoid(pv.x), p1 = fsigmoid(pv.y);
        float p2 = fsigmoid(pv.z), p3 = fsigmoid(pv.w);

        float c0 = p0 * fabsf(s0), c1 = p1 * fabsf(s1);
        float c2 = p2 * fabsf(s2), c3 = p3 * fabsf(s3);

        int base = 4 * i;
        oc[base] = c0;
        *(float2*)(oc + base + 1) = make_float2(c1, c2);
        oc[base + 3] = c3;

        float q0 = fminf(fmaxf(p0, EPSV), 1.0f - EPSV);
        float q1 = fminf(fmaxf(p1, EPSV), 1.0f - EPSV);
        float q2 = fminf(fmaxf(p2, EPSV), 1.0f - EPSV);
        float q3 = fminf(fmaxf(p3, EPSV), 1.0f - EPSV);

        float g0 = 1.0f - fabsf(tv.x - q0);
        float g1 = 1.0f - fabsf(tv.y - q1);
        float g2 = 1.0f - fabsf(tv.z - q2);
        float g3 = 1.0f - fabsf(tv.w - q3);

        bool k0 = (tv.x > 0.0f) || (s0 < 0.0f);
        bool k1 = (tv.y > 0.0f) || (s1 < 0.0f);
        bool k2 = (tv.z > 0.0f) || (s2 < 0.0f);
        bool k3 = (tv.w > 0.0f) || (s3 < 0.0f);

        acc += k0 ? __logf(g0) : 0.0f;
        acc += k1 ? __logf(g1) : 0.0f;
        acc += k2 ? __logf(g2) : 0.0f;
        acc += k3 ? __logf(g3) : 0.0f;
    }

    // Block reduction.
    #pragma unroll
    for (int o = 16; o > 0; o >>= 1)
        acc += __shfl_xor_sync(0xFFFFFFFFu, acc, o);
    if ((tid & 31) == 0) red[tid >> 5] = acc;
    __syncthreads();
    if (tid == 0) {
        float v = red[0];
        #pragma unroll
        for (int w = 1; w < 8; w++) v += red[w];
        g_partial[b] = v;
        __threadfence();
        int prev = atomicAdd(&g_done, 1);
        is_last = (prev == (int)gridDim.x - 1);
    }
    __syncthreads();

    if (is_last) {
        __threadfence();
        double s = 0.0;
        for (int i = tid; i < BB; i += 256) s += (double)g_partial[i];
        #pragma unroll
        for (int o = 16; o > 0; o >>= 1)
            s += __shfl_xor_sync(0xFFFFFFFFu, s, o);
        if ((tid & 31) == 0) dred[tid >> 5] = s;
        __syncthreads();
        if (tid == 0) {
            double v = 0.0;
            #pragma unroll
            for (int w = 0; w < 8; w++) v += dred[w];
            out[0] = (float)(-v / (double)BB);
            g_done = 0;
        }
    }
}

extern "C" void kernel_launch(void* const* d_in, const int* in_sizes, int n_in,
                              void* d_out, int out_size) {
    const float* pred   = (const float*)d_in[0];
    const float* target = (const float*)d_in[1];
    const int*   parent = (const int*)d_in[2];

    const int N = in_sizes[2];     // 8192
    const int B = in_sizes[0] / N; // 4096

    float* out = (float*)d_out;

    anc_setup_kernel<<<(N + 255) / 256, 256>>>(parent, N);
    cond_sigmoid_kernel<<<B, 256>>>(pred, target, out);
}